// round 5
// baseline (speedup 1.0000x reference)
#include <cuda_runtime.h>
#include <math_constants.h>

// B=4, N=M=4096, D=3; scalar fp32 output
#define BATCH   4
#define NPTS    4096
#define TPB     128
#define RQ      4                        // queries per thread
#define QPB     (TPB * RQ)               // 512 queries per block
#define QCHUNKS (NPTS / QPB)             // 8
#define SSPLIT  16                       // target-range splits (blocks per group)
#define TILE_T  (NPTS / SSPLIT)          // 256 targets per block
#define NBLOCKS (2 * BATCH * QCHUNKS * SSPLIT)   // 1024
#define NGROUPS (2 * BATCH * QCHUNKS)    // 64 (32 per direction)
#define NQ_TOT  (2 * BATCH * NPTS)       // 32768 query jobs

// Scratch: partial min (of s = 0.5||t||^2 - q.t) per (query-job, split): 2 MB
__device__ float g_partial[NQ_TOT * SSPLIT];
__device__ float g_gsum[NGROUPS];                 // per-group sums of d2
__device__ unsigned int g_gcount[NGROUPS];        // zero-init; self-resetting
__device__ unsigned int g_gdone;                  // zero-init; self-resetting

typedef unsigned long long ull;

__device__ __forceinline__ ull pack2(float v) {
    ull r;
    asm("mov.b64 %0, {%1, %1};" : "=l"(r) : "f"(v));
    return r;
}
__device__ __forceinline__ ull fma2(ull a, ull b, ull c) {
    ull d;
    asm("fma.rn.f32x2 %0, %1, %2, %3;" : "=l"(d) : "l"(a), "l"(b), "l"(c));
    return d;
}
__device__ __forceinline__ void min2(float& m0, float& m1, ull s) {
    float lo, hi;
    asm("mov.b64 {%0, %1}, %2;" : "=f"(lo), "=f"(hi) : "l"(s));
    m0 = fminf(m0, lo);
    m1 = fminf(m1, hi);
}

__global__ __launch_bounds__(TPB)
void chamfer_fused_kernel(const float* __restrict__ X, const float* __restrict__ Y,
                          float* __restrict__ out) {
    const int bid = blockIdx.x;
    const int s   = bid & (SSPLIT - 1);          // bits 0-3
    const int qc  = (bid >> 4) & (QCHUNKS - 1);  // bits 4-6
    const int b   = (bid >> 7) & (BATCH - 1);    // bits 7-8
    const int dir = bid >> 9;                    // bit 9
    const int grp = (dir * BATCH + b) * QCHUNKS + qc;   // 0..63

    const float* __restrict__ Q = dir ? Y : X;
    const float* __restrict__ T = dir ? X : Y;

    __shared__ __align__(16) float sx0[TILE_T];
    __shared__ __align__(16) float sx1[TILE_T];
    __shared__ __align__(16) float sx2[TILE_T];
    __shared__ __align__(16) float swv[TILE_T];

    // ---- Phase 1: this split's partial mins --------------------------------
    const int tb = s * TILE_T;
    for (int t = threadIdx.x; t < TILE_T; t += TPB) {
        const float* tp = T + ((size_t)b * NPTS + tb + t) * 3;
        const float a0 = tp[0], a1 = tp[1], a2 = tp[2];
        sx0[t] = a0; sx1[t] = a1; sx2[t] = a2;
        swv[t] = 0.5f * (a0 * a0 + a1 * a1 + a2 * a2);
    }

    const int q0 = qc * QPB + threadIdx.x;
    ull nx[RQ], ny[RQ], nz[RQ];
    #pragma unroll
    for (int r = 0; r < RQ; r++) {
        const int q = q0 + r * TPB;
        const float* qp = Q + ((size_t)b * NPTS + q) * 3;
        nx[r] = pack2(-qp[0]); ny[r] = pack2(-qp[1]); nz[r] = pack2(-qp[2]);
    }
    __syncthreads();

    float m0[RQ], m1[RQ];
    #pragma unroll
    for (int r = 0; r < RQ; r++) { m0[r] = CUDART_INF_F; m1[r] = CUDART_INF_F; }

    const ulonglong2* px = (const ulonglong2*)sx0;
    const ulonglong2* py = (const ulonglong2*)sx1;
    const ulonglong2* pz = (const ulonglong2*)sx2;
    const ulonglong2* pw = (const ulonglong2*)swv;

    #pragma unroll 2
    for (int g = 0; g < TILE_T / 4; g++) {
        const ulonglong2 Xv = px[g];
        const ulonglong2 Yv = py[g];
        const ulonglong2 Zv = pz[g];
        const ulonglong2 Wv = pw[g];
        #pragma unroll
        for (int r = 0; r < RQ; r++) {
            // s = 0.5||t||^2 - q.t  (two targets per packed op)
            const ull s01 = fma2(nx[r], Xv.x, fma2(ny[r], Yv.x, fma2(nz[r], Zv.x, Wv.x)));
            const ull s23 = fma2(nx[r], Xv.y, fma2(ny[r], Yv.y, fma2(nz[r], Zv.y, Wv.y)));
            min2(m0[r], m1[r], s01);
            min2(m0[r], m1[r], s23);
        }
    }

    #pragma unroll
    for (int r = 0; r < RQ; r++) {
        const int q = q0 + r * TPB;
        const int item = (dir * BATCH + b) * NPTS + q;
        g_partial[item * SSPLIT + s] = fminf(m0[r], m1[r]);
    }

    // ---- Phase 2: group ticket; last split-block of the group reduces it ---
    __shared__ unsigned int tk;
    if (threadIdx.x == 0) {
        __threadfence();
        tk = atomicAdd(&g_gcount[grp], 1u);
    }
    __syncthreads();
    if (tk != SSPLIT - 1) return;
    __threadfence();   // acquire: siblings' partials now visible

    const int base_item = (dir * BATCH + b) * NPTS + qc * QPB;
    float lsum = 0.0f;
    #pragma unroll
    for (int k = 0; k < RQ; k++) {
        const int qi = threadIdx.x + k * TPB;                    // 0..511
        const float4* pr = (const float4*)(g_partial + (size_t)(base_item + qi) * SSPLIT);
        float4 v0 = __ldcg(&pr[0]);
        float4 v1 = __ldcg(&pr[1]);
        float4 v2 = __ldcg(&pr[2]);
        float4 v3 = __ldcg(&pr[3]);
        float m = fminf(fminf(fminf(v0.x, v0.y), fminf(v0.z, v0.w)),
                        fminf(fminf(v1.x, v1.y), fminf(v1.z, v1.w)));
        m = fminf(m, fminf(fminf(fminf(v2.x, v2.y), fminf(v2.z, v2.w)),
                           fminf(fminf(v3.x, v3.y), fminf(v3.z, v3.w))));
        const float* qp = Q + ((size_t)b * NPTS + qc * QPB + qi) * 3;
        const float a = qp[0], c = qp[1], d = qp[2];
        const float qn = a * a + c * c + d * d;
        lsum += fmaxf(fmaf(2.0f, m, qn), 0.0f);
    }

    // Deterministic block sum
    __shared__ float wsum[TPB / 32];
    #pragma unroll
    for (int o = 16; o > 0; o >>= 1)
        lsum += __shfl_xor_sync(0xFFFFFFFFu, lsum, o);
    const int wid  = threadIdx.x >> 5;
    const int lane = threadIdx.x & 31;
    if (lane == 0) wsum[wid] = lsum;
    __syncthreads();

    __shared__ unsigned int gtk;
    if (threadIdx.x == 0) {
        float ssum = 0.0f;
        #pragma unroll
        for (int w = 0; w < TPB / 32; w++) ssum += wsum[w];
        g_gsum[grp] = ssum;
        g_gcount[grp] = 0u;              // reset group counter for next replay
        __threadfence();
        gtk = atomicAdd(&g_gdone, 1u);
    }
    __syncthreads();
    if (gtk != NGROUPS - 1) return;
    __threadfence();   // acquire: all group sums visible

    // ---- Phase 3: final reduction (single last block) ----------------------
    if (threadIdx.x < 32) {
        // g_gsum[0:32) = dir0, [32:64) = dir1
        float s0 = __ldcg(&g_gsum[threadIdx.x]);
        float s1 = __ldcg(&g_gsum[32 + threadIdx.x]);
        #pragma unroll
        for (int o = 16; o > 0; o >>= 1) {
            s0 += __shfl_xor_sync(0xFFFFFFFFu, s0, o);
            s1 += __shfl_xor_sync(0xFFFFFFFFu, s1, o);
        }
        if (threadIdx.x == 0) {
            out[0] = fmaxf(s0, s1) * (1.0f / (float)(BATCH * NPTS));
            g_gdone = 0u;                // reset for next replay
        }
    }
}

extern "C" void kernel_launch(void* const* d_in, const int* in_sizes, int n_in,
                              void* d_out, int out_size) {
    const float* x = (const float*)d_in[0];
    const float* y = (const float*)d_in[1];
    float* out = (float*)d_out;

    chamfer_fused_kernel<<<NBLOCKS, TPB>>>(x, y, out);
}

// round 6
// speedup vs baseline: 1.0667x; 1.0667x over previous
#include <cuda_runtime.h>
#include <math_constants.h>

// B=4, N=M=4096, D=3; scalar fp32 output
#define BATCH   4
#define NPTS    4096
#define TPB     128
#define RQ      4                        // queries per thread
#define QPB     (TPB * RQ)               // 512 queries per block
#define QCHUNKS (NPTS / QPB)             // 8
#define SSPLIT  16                       // target-range splits (blocks per group)
#define TILE_T  (NPTS / SSPLIT)          // 256 targets per block
#define NBLOCKS (2 * BATCH * QCHUNKS * SSPLIT)   // 1024 (single co-resident wave)
#define NGROUPS (2 * BATCH * QCHUNKS)    // 64
#define NQ_TOT  (2 * BATCH * NPTS)       // 32768 query jobs
#define QPFIN   (QPB / SSPLIT)           // 32 queries per block in finisher

// Scratch: partial min (of s = 0.5||t||^2 - q.t) per (query-job, split): 2 MB
__device__ float g_partial[NQ_TOT * SSPLIT];
__device__ float g_blocksum[NBLOCKS];
__device__ unsigned int g_gcount[NGROUPS];        // zero-init; reset by last block
__device__ unsigned int g_gdone;                  // zero-init; reset by last block

typedef unsigned long long ull;

__device__ __forceinline__ ull pack2(float v) {
    ull r;
    asm("mov.b64 %0, {%1, %1};" : "=l"(r) : "f"(v));
    return r;
}
__device__ __forceinline__ ull fma2(ull a, ull b, ull c) {
    ull d;
    asm("fma.rn.f32x2 %0, %1, %2, %3;" : "=l"(d) : "l"(a), "l"(b), "l"(c));
    return d;
}
__device__ __forceinline__ void min2(float& m0, float& m1, ull s) {
    float lo, hi;
    asm("mov.b64 {%0, %1}, %2;" : "=f"(lo), "=f"(hi) : "l"(s));
    m0 = fminf(m0, lo);
    m1 = fminf(m1, hi);
}

__global__ __launch_bounds__(TPB, 8)   // cap regs at 64 -> 8 blocks/SM -> grid fully resident
void chamfer_fused_kernel(const float* __restrict__ X, const float* __restrict__ Y,
                          float* __restrict__ out) {
    const int bid = blockIdx.x;
    const int s   = bid & (SSPLIT - 1);          // bits 0-3
    const int qc  = (bid >> 4) & (QCHUNKS - 1);  // bits 4-6
    const int b   = (bid >> 7) & (BATCH - 1);    // bits 7-8
    const int dir = bid >> 9;                    // bit 9
    const int grp = (dir * BATCH + b) * QCHUNKS + qc;   // 0..63

    const float* __restrict__ Q = dir ? Y : X;
    const float* __restrict__ T = dir ? X : Y;

    __shared__ __align__(16) float sx0[TILE_T];
    __shared__ __align__(16) float sx1[TILE_T];
    __shared__ __align__(16) float sx2[TILE_T];
    __shared__ __align__(16) float swv[TILE_T];

    // ---- Phase 1: this split's partial mins --------------------------------
    const int tb = s * TILE_T;
    for (int t = threadIdx.x; t < TILE_T; t += TPB) {
        const float* tp = T + ((size_t)b * NPTS + tb + t) * 3;
        const float a0 = tp[0], a1 = tp[1], a2 = tp[2];
        sx0[t] = a0; sx1[t] = a1; sx2[t] = a2;
        swv[t] = 0.5f * (a0 * a0 + a1 * a1 + a2 * a2);
    }

    const int q0 = qc * QPB + threadIdx.x;
    ull nx[RQ], ny[RQ], nz[RQ];
    #pragma unroll
    for (int r = 0; r < RQ; r++) {
        const int q = q0 + r * TPB;
        const float* qp = Q + ((size_t)b * NPTS + q) * 3;
        nx[r] = pack2(-qp[0]); ny[r] = pack2(-qp[1]); nz[r] = pack2(-qp[2]);
    }
    __syncthreads();

    float m0[RQ], m1[RQ];
    #pragma unroll
    for (int r = 0; r < RQ; r++) { m0[r] = CUDART_INF_F; m1[r] = CUDART_INF_F; }

    const ulonglong2* px = (const ulonglong2*)sx0;
    const ulonglong2* py = (const ulonglong2*)sx1;
    const ulonglong2* pz = (const ulonglong2*)sx2;
    const ulonglong2* pw = (const ulonglong2*)swv;

    #pragma unroll 4
    for (int g = 0; g < TILE_T / 4; g++) {
        const ulonglong2 Xv = px[g];
        const ulonglong2 Yv = py[g];
        const ulonglong2 Zv = pz[g];
        const ulonglong2 Wv = pw[g];
        #pragma unroll
        for (int r = 0; r < RQ; r++) {
            // s = 0.5||t||^2 - q.t  (two targets per packed op)
            const ull s01 = fma2(nx[r], Xv.x, fma2(ny[r], Yv.x, fma2(nz[r], Zv.x, Wv.x)));
            const ull s23 = fma2(nx[r], Xv.y, fma2(ny[r], Yv.y, fma2(nz[r], Zv.y, Wv.y)));
            min2(m0[r], m1[r], s01);
            min2(m0[r], m1[r], s23);
        }
    }

    #pragma unroll
    for (int r = 0; r < RQ; r++) {
        const int q = q0 + r * TPB;
        const int item = (dir * BATCH + b) * NPTS + q;
        g_partial[item * SSPLIT + s] = fminf(m0[r], m1[r]);
    }

    // ---- Phase 2: arrive + spin until whole group done (all blocks resident)
    if (threadIdx.x == 0) {
        __threadfence();
        atomicAdd(&g_gcount[grp], 1u);
    }
    __syncthreads();
    if (threadIdx.x == 0) {
        while (*(volatile unsigned int*)&g_gcount[grp] < SSPLIT) __nanosleep(32);
    }
    __syncthreads();
    __threadfence();   // acquire: all 16 siblings' partials visible

    // ---- Phase 3: each block reduces its own 32-query slice ----------------
    // thread t: query ql = t>>2 within slice, partial-quarter k = t&3
    const int ql = threadIdx.x >> 2;
    const int k  = threadIdx.x & 3;
    const int q  = qc * QPB + s * QPFIN + ql;
    const int item = (dir * BATCH + b) * NPTS + q;

    const float4 v = __ldcg((const float4*)(g_partial + (size_t)item * SSPLIT + k * 4));
    float m = fminf(fminf(v.x, v.y), fminf(v.z, v.w));
    m = fminf(m, __shfl_xor_sync(0xFFFFFFFFu, m, 1));
    m = fminf(m, __shfl_xor_sync(0xFFFFFFFFu, m, 2));   // all 4 lanes of quad: min of 16

    float lsum = 0.0f;
    if (k == 0) {
        const float* qp = Q + ((size_t)b * NPTS + q) * 3;
        const float a = qp[0], c = qp[1], d = qp[2];
        const float qn = a * a + c * c + d * d;
        lsum = fmaxf(fmaf(2.0f, m, qn), 0.0f);
    }
    #pragma unroll
    for (int o = 16; o > 0; o >>= 1)
        lsum += __shfl_xor_sync(0xFFFFFFFFu, lsum, o);

    __shared__ float wsum[TPB / 32];
    const int wid  = threadIdx.x >> 5;
    const int lane = threadIdx.x & 31;
    if (lane == 0) wsum[wid] = lsum;
    __syncthreads();

    __shared__ unsigned int gtk;
    if (threadIdx.x == 0) {
        float ssum = 0.0f;
        #pragma unroll
        for (int w = 0; w < TPB / 32; w++) ssum += wsum[w];
        g_blocksum[bid] = ssum;
        __threadfence();
        gtk = atomicAdd(&g_gdone, 1u);
    }
    __syncthreads();
    if (gtk != NBLOCKS - 1) return;
    __threadfence();   // acquire: all block sums visible

    // ---- Phase 4: globally-last block: final reduce + counter reset --------
    {
        // blocksum[0:512)=dir0, [512:1024)=dir1 ; 4 values per thread per dir
        float s0 = 0.0f, s1 = 0.0f;
        #pragma unroll
        for (int j = 0; j < 4; j++) {
            s0 += __ldcg(&g_blocksum[threadIdx.x + j * TPB]);
            s1 += __ldcg(&g_blocksum[512 + threadIdx.x + j * TPB]);
        }
        #pragma unroll
        for (int o = 16; o > 0; o >>= 1) {
            s0 += __shfl_xor_sync(0xFFFFFFFFu, s0, o);
            s1 += __shfl_xor_sync(0xFFFFFFFFu, s1, o);
        }
        __shared__ float f0[TPB / 32], f1[TPB / 32];
        if (lane == 0) { f0[wid] = s0; f1[wid] = s1; }
        __syncthreads();
        if (threadIdx.x < NGROUPS) g_gcount[threadIdx.x] = 0u;   // reset group counters
        if (threadIdx.x == 0) {
            float a0 = 0.0f, a1 = 0.0f;
            #pragma unroll
            for (int w = 0; w < TPB / 32; w++) { a0 += f0[w]; a1 += f1[w]; }
            out[0] = fmaxf(a0, a1) * (1.0f / (float)(BATCH * NPTS));
            g_gdone = 0u;                                        // reset for next replay
        }
    }
}

extern "C" void kernel_launch(void* const* d_in, const int* in_sizes, int n_in,
                              void* d_out, int out_size) {
    const float* x = (const float*)d_in[0];
    const float* y = (const float*)d_in[1];
    float* out = (float*)d_out;

    chamfer_fused_kernel<<<NBLOCKS, TPB>>>(x, y, out);
}